// round 1
// baseline (speedup 1.0000x reference)
#include <cuda_runtime.h>
#include <cstdint>
#include <cstddef>

#define HID 128
#define LDSX 132   // shared-memory row stride (floats): 128 + 4 pad, keeps 16B alignment

// ---------------- device scratch (no allocations allowed) ----------------
__device__ float g_A[HID * HID];        // Wo @ W_mo
__device__ float g_B[HID * HID];        // Wiv @ Wv
__device__ float g_u[HID];              // Wiv @ bv + biv
__device__ float g_w[HID];              // Wo @ b_mo + bo
__device__ float g_Bfrag[16 * 16 * 32 * 2]; // 0.5*M^T in tf32, per-mma-fragment layout
__device__ float g_c[HID];              // 0.5 * (A @ u + w)

__device__ __forceinline__ uint32_t f2tf32(float x) {
    uint32_t r;
    asm("cvt.rna.tf32.f32 %0, %1;" : "=r"(r) : "f"(x));
    return r;
}

// ---------------- prep kernel 1: A = Wo@W_mo, B = Wiv@Wv, u, w -----------
__global__ void prep1(const float* __restrict__ Wo, const float* __restrict__ W_mo,
                      const float* __restrict__ W_in, const float* __restrict__ Wv,
                      const float* __restrict__ bv, const float* __restrict__ b_in,
                      const float* __restrict__ b_mo, const float* __restrict__ bo)
{
    int g = blockIdx.x * blockDim.x + threadIdx.x;
    if (g < HID * HID) {
        int r = g >> 7, c = g & 127;
        float s = 0.f;
        #pragma unroll 8
        for (int j = 0; j < HID; ++j) s += Wo[r * HID + j] * W_mo[j * HID + c];
        g_A[g] = s;
    } else if (g < 2 * HID * HID) {
        int idx = g - HID * HID;
        int p = idx >> 7, i = idx & 127;
        float s = 0.f;
        #pragma unroll 8
        for (int m = 0; m < HID; ++m) s += W_in[(256 + p) * HID + m] * Wv[m * HID + i];
        g_B[idx] = s;
    } else if (g < 2 * HID * HID + HID) {
        int p = g - 2 * HID * HID;
        float s = 0.f;
        for (int m = 0; m < HID; ++m) s += W_in[(256 + p) * HID + m] * bv[m];
        g_u[p] = s + b_in[256 + p];
    } else if (g < 2 * HID * HID + 2 * HID) {
        int k = g - 2 * HID * HID - HID;
        float s = 0.f;
        for (int j = 0; j < HID; ++j) s += Wo[k * HID + j] * b_mo[j];
        g_w[k] = s + bo[k];
    }
}

// ---------------- prep kernel 2: M = A@B folded into fragment layout -----
// Main GEMM: Y[e][o] = sum_i X[e][i] * M'[o][i],  M' = 0.5*M.
// mma B operand (col-major, 8x8 = k x n): Bmat[i][o] = M'[o][i].
// Fragment element for (kstep ks, ntile nt, lane l):
//   b0 = Bmat[8ks + l%4    ][8nt + l/4] = M'[8nt + l/4][8ks + l%4]
//   b1 = Bmat[8ks + l%4 + 4][8nt + l/4] = M'[8nt + l/4][8ks + l%4 + 4]
// stored at g_Bfrag[((ks*16 + nt)*32 + l)*2 + {0,1}]  (tf32 bit pattern).
__global__ void prep2()
{
    int g = blockIdx.x * blockDim.x + threadIdx.x;
    if (g < 8192) {
        int lane = g & 31, nt = (g >> 5) & 15, ks = g >> 9;
        int o  = nt * 8 + (lane >> 2);
        int i0 = ks * 8 + (lane & 3);
        float s0 = 0.f, s1 = 0.f;
        #pragma unroll 8
        for (int j = 0; j < HID; ++j) {
            float a = g_A[o * HID + j];
            s0 += a * g_B[j * HID + i0];
            s1 += a * g_B[j * HID + i0 + 4];
        }
        g_Bfrag[2 * g]     = __uint_as_float(f2tf32(0.5f * s0));
        g_Bfrag[2 * g + 1] = __uint_as_float(f2tf32(0.5f * s1));
    } else if (g < 8192 + HID) {
        int k = g - 8192;
        float s = 0.f;
        for (int j = 0; j < HID; ++j) s += g_A[k * HID + j] * g_u[j];
        g_c[k] = 0.5f * (s + g_w[k]);
    }
}

// ---------------- main fused kernel: Y = X + X@M'^T + c ------------------
// Block: 256 threads (8 warps), tile BM=128 rows x full N=128, full K=128.
// Warp grid 4(m) x 2(n); warp tile m32 x n64 -> 2 m-tiles x 8 n-tiles of m16n8k8.
__global__ __launch_bounds__(256) void fused_main(
    const float* __restrict__ X, float* __restrict__ Y, int E)
{
    extern __shared__ float Xs[];  // [128][LDSX]
    int tid  = threadIdx.x;
    int row0 = blockIdx.x * 128;

    // Load X tile (float4, coalesced), zero-fill past E (no OOB reads)
    #pragma unroll
    for (int it = 0; it < 16; ++it) {
        int idx = tid + it * 256;
        int r = idx >> 5, c4 = idx & 31;
        int grow = row0 + r;
        float4 v = make_float4(0.f, 0.f, 0.f, 0.f);
        if (grow < E)
            v = *reinterpret_cast<const float4*>(X + (size_t)grow * HID + c4 * 4);
        *reinterpret_cast<float4*>(&Xs[r * LDSX + c4 * 4]) = v;
    }
    __syncthreads();

    int lane = tid & 31, wid = tid >> 5;
    int wm = wid & 3, wn = wid >> 2;
    int lq = lane >> 2, lr = lane & 3;
    int mrow0 = wm * 32;

    float acc[2][8][4];
    #pragma unroll
    for (int mt = 0; mt < 2; ++mt)
        #pragma unroll
        for (int nt = 0; nt < 8; ++nt)
            #pragma unroll
            for (int q = 0; q < 4; ++q) acc[mt][nt][q] = 0.f;

    const float2* bfr = reinterpret_cast<const float2*>(g_Bfrag);

    #pragma unroll
    for (int ks = 0; ks < 16; ++ks) {
        uint32_t a[2][4];
        #pragma unroll
        for (int mt = 0; mt < 2; ++mt) {
            int rb = mrow0 + mt * 16 + lq;
            int cb = ks * 8 + lr;
            // conflict-free: bank = (lq*4 + lr) covers 0..31 distinct
            a[mt][0] = f2tf32(Xs[rb * LDSX + cb]);
            a[mt][1] = f2tf32(Xs[(rb + 8) * LDSX + cb]);
            a[mt][2] = f2tf32(Xs[rb * LDSX + cb + 4]);
            a[mt][3] = f2tf32(Xs[(rb + 8) * LDSX + cb + 4]);
        }
        #pragma unroll
        for (int nt = 0; nt < 8; ++nt) {
            int gnt = wn * 8 + nt;
            float2 bb = bfr[(ks * 16 + gnt) * 32 + lane];  // coalesced, L1-hot
            uint32_t b0 = __float_as_uint(bb.x);
            uint32_t b1 = __float_as_uint(bb.y);
            #pragma unroll
            for (int mt = 0; mt < 2; ++mt) {
                asm volatile(
                    "mma.sync.aligned.m16n8k8.row.col.f32.tf32.tf32.f32 "
                    "{%0,%1,%2,%3}, {%4,%5,%6,%7}, {%8,%9}, {%0,%1,%2,%3};\n"
                    : "+f"(acc[mt][nt][0]), "+f"(acc[mt][nt][1]),
                      "+f"(acc[mt][nt][2]), "+f"(acc[mt][nt][3])
                    : "r"(a[mt][0]), "r"(a[mt][1]), "r"(a[mt][2]), "r"(a[mt][3]),
                      "r"(b0), "r"(b1));
            }
        }
    }

    // Epilogue: residual (fp32 from shared) + bias, float2 stores
    #pragma unroll
    for (int mt = 0; mt < 2; ++mt) {
        int r = mrow0 + mt * 16 + lq;
        int grow = row0 + r;
        #pragma unroll
        for (int nt = 0; nt < 8; ++nt) {
            int col = wn * 64 + nt * 8 + lr * 2;
            float cv0 = g_c[col], cv1 = g_c[col + 1];
            if (grow < E) {
                float2 o0;
                o0.x = Xs[r * LDSX + col]     + acc[mt][nt][0] + cv0;
                o0.y = Xs[r * LDSX + col + 1] + acc[mt][nt][1] + cv1;
                *reinterpret_cast<float2*>(Y + (size_t)grow * HID + col) = o0;
            }
            if (grow + 8 < E) {
                float2 o1;
                o1.x = Xs[(r + 8) * LDSX + col]     + acc[mt][nt][2] + cv0;
                o1.y = Xs[(r + 8) * LDSX + col + 1] + acc[mt][nt][3] + cv1;
                *reinterpret_cast<float2*>(Y + (size_t)(grow + 8) * HID + col) = o1;
            }
        }
    }
}

// ---------------- launch ----------------
extern "C" void kernel_launch(void* const* d_in, const int* in_sizes, int n_in,
                              void* d_out, int out_size)
{
    const float* X    = (const float*)d_in[0];
    const float* Wv   = (const float*)d_in[7];
    const float* bv   = (const float*)d_in[8];
    const float* W_in = (const float*)d_in[9];
    const float* b_in = (const float*)d_in[10];
    const float* W_mo = (const float*)d_in[11];
    const float* b_mo = (const float*)d_in[12];
    const float* Wo   = (const float*)d_in[13];
    const float* bo   = (const float*)d_in[14];
    float* Y = (float*)d_out;

    int E = in_sizes[0] / HID;

    prep1<<<129, 256>>>(Wo, W_mo, W_in, Wv, bv, b_in, b_mo, bo);
    prep2<<<33, 256>>>();

    const int smem = 128 * LDSX * 4;  // 67,584 bytes
    cudaFuncSetAttribute(fused_main, cudaFuncAttributeMaxDynamicSharedMemorySize, smem);
    int blocks = (E + 127) / 128;
    fused_main<<<blocks, 256, smem>>>(X, Y, E);
}

// round 2
// speedup vs baseline: 1.1783x; 1.1783x over previous
#include <cuda_runtime.h>
#include <cstdint>
#include <cstddef>

#define HID 128
#define LDSX 132          // padded row stride (floats)
#define BM 64             // rows per tile
#define NTHREADS 256
#define PBLOCKS 444       // 3 per SM * 148 SMs, persistent

// ---------------- device scratch ----------------
__device__ float g_A[HID * HID];            // Wo @ W_mo
__device__ float g_B[HID * HID];            // Wiv @ Wv
__device__ float g_u[HID];                  // Wiv @ bv + biv
__device__ float g_w[HID];                  // Wo @ b_mo + bo
__device__ float g_Bfrag[16 * 16 * 32 * 2]; // 0.5*M^T, tf32, mma-fragment layout
__device__ float g_c[HID];                  // 0.5 * (A @ u + w)

__device__ __forceinline__ uint32_t f2tf32(float x) {
    uint32_t r;
    asm("cvt.rna.tf32.f32 %0, %1;" : "=r"(r) : "f"(x));
    return r;
}

// ---------------- prep1: A = Wo@W_mo, B = Wiv@Wv, u, w (128 blocks) -------
__global__ __launch_bounds__(256) void prep1(
    const float* __restrict__ Wo, const float* __restrict__ W_mo,
    const float* __restrict__ W_in, const float* __restrict__ Wv,
    const float* __restrict__ bv, const float* __restrict__ b_in,
    const float* __restrict__ b_mo, const float* __restrict__ bo)
{
    __shared__ float sWo[HID];
    __shared__ float sWiv[HID];
    const int r = blockIdx.x;
    const int t = threadIdx.x;

    if (t < HID) sWo[t] = Wo[r * HID + t];
    else         sWiv[t - HID] = W_in[(256 + r) * HID + (t - HID)];
    __syncthreads();

    if (t < HID) {
        float s0 = 0.f, s1 = 0.f, s2 = 0.f, s3 = 0.f;
        #pragma unroll
        for (int j = 0; j < HID; j += 4) {
            s0 += sWo[j]     * W_mo[j * HID + t];
            s1 += sWo[j + 1] * W_mo[(j + 1) * HID + t];
            s2 += sWo[j + 2] * W_mo[(j + 2) * HID + t];
            s3 += sWo[j + 3] * W_mo[(j + 3) * HID + t];
        }
        g_A[r * HID + t] = (s0 + s1) + (s2 + s3);
        if (t == 0) {
            float a0 = 0.f, a1 = 0.f, a2 = 0.f, a3 = 0.f;
            #pragma unroll
            for (int j = 0; j < HID; j += 4) {
                a0 += sWiv[j] * bv[j];     a1 += sWiv[j + 1] * bv[j + 1];
                a2 += sWiv[j + 2] * bv[j + 2]; a3 += sWiv[j + 3] * bv[j + 3];
            }
            g_u[r] = (a0 + a1) + (a2 + a3) + b_in[256 + r];
        }
    } else {
        const int c = t - HID;
        float s0 = 0.f, s1 = 0.f, s2 = 0.f, s3 = 0.f;
        #pragma unroll
        for (int j = 0; j < HID; j += 4) {
            s0 += sWiv[j]     * Wv[j * HID + c];
            s1 += sWiv[j + 1] * Wv[(j + 1) * HID + c];
            s2 += sWiv[j + 2] * Wv[(j + 2) * HID + c];
            s3 += sWiv[j + 3] * Wv[(j + 3) * HID + c];
        }
        g_B[r * HID + c] = (s0 + s1) + (s2 + s3);
        if (c == 0) {
            float a0 = 0.f, a1 = 0.f, a2 = 0.f, a3 = 0.f;
            #pragma unroll
            for (int j = 0; j < HID; j += 4) {
                a0 += sWo[j] * b_mo[j];     a1 += sWo[j + 1] * b_mo[j + 1];
                a2 += sWo[j + 2] * b_mo[j + 2]; a3 += sWo[j + 3] * b_mo[j + 3];
            }
            g_w[r] = (a0 + a1) + (a2 + a3) + bo[r];
        }
    }
}

// ---------------- prep2: M = 0.5*A@B -> fragment layout; c (128 blocks) ---
__global__ __launch_bounds__(128) void prep2()
{
    __shared__ float sA[HID];
    const int o = blockIdx.x;
    const int i = threadIdx.x;

    sA[i] = g_A[o * HID + i];
    __syncthreads();

    float s0 = 0.f, s1 = 0.f, s2 = 0.f, s3 = 0.f;
    #pragma unroll
    for (int j = 0; j < HID; j += 4) {
        s0 += sA[j]     * g_B[j * HID + i];
        s1 += sA[j + 1] * g_B[(j + 1) * HID + i];
        s2 += sA[j + 2] * g_B[(j + 2) * HID + i];
        s3 += sA[j + 3] * g_B[(j + 3) * HID + i];
    }
    float m = 0.5f * ((s0 + s1) + (s2 + s3));

    // scatter M'[o][i] into the mma B-fragment layout:
    //   ks = i>>3, lr = i&3, half = (i>>2)&1, nt = o>>3, lq = o&7
    const int nt = o >> 3, lq = o & 7;
    const int ks = i >> 3, lr = i & 3, half = (i >> 2) & 1;
    g_Bfrag[(((ks * 16 + nt) * 32) + lq * 4 + lr) * 2 + half] =
        __uint_as_float(f2tf32(m));

    if (i == 0) {
        float a0 = 0.f, a1 = 0.f, a2 = 0.f, a3 = 0.f;
        #pragma unroll
        for (int j = 0; j < HID; j += 4) {
            a0 += sA[j] * g_u[j];     a1 += sA[j + 1] * g_u[j + 1];
            a2 += sA[j + 2] * g_u[j + 2]; a3 += sA[j + 3] * g_u[j + 3];
        }
        g_c[o] = 0.5f * (((a0 + a1) + (a2 + a3)) + g_w[o]);
    }
}

// ---------------- main: Y = X + X@M'^T + c, persistent + double-buffered --
__device__ __forceinline__ void cp_async16(uint32_t dst, const void* src, int sz) {
    asm volatile("cp.async.cg.shared.global [%0], [%1], 16, %2;\n"
                 :: "r"(dst), "l"(src), "r"(sz));
}

__global__ __launch_bounds__(NTHREADS, 3) void fused_main(
    const float* __restrict__ X, float* __restrict__ Y, int E, int ntiles)
{
    extern __shared__ float Xs[];  // 2 stages x [BM][LDSX]
    const int tid  = threadIdx.x;
    const int lane = tid & 31, wid = tid >> 5;
    const int wm = wid & 1, wn = wid >> 1;          // 2(m) x 4(n) warp grid
    const int lq = lane >> 2, lr = lane & 3;

    uint32_t sbase;
    asm("{ .reg .u64 t; cvta.to.shared.u64 t, %1; cvt.u32.u64 %0, t; }"
        : "=r"(sbase) : "l"(Xs));

    const float2* bfr = reinterpret_cast<const float2*>(g_Bfrag);

    // per-thread output bias (constant across tiles)
    float cv[4][2];
    #pragma unroll
    for (int nt = 0; nt < 4; ++nt) {
        int col = wn * 32 + nt * 8 + lr * 2;
        cv[nt][0] = g_c[col];
        cv[nt][1] = g_c[col + 1];
    }

    int t = blockIdx.x;
    const int stride = gridDim.x;
    if (t >= ntiles) return;

    // --- async tile loader: 8 x 16B per thread = 32KB tile ---
    auto load_tile = [&](int stage, int tt) {
        const int row0 = tt * BM;
        #pragma unroll
        for (int it = 0; it < 8; ++it) {
            int idx = it * NTHREADS + tid;       // 0..2047
            int rr = idx >> 5, c4 = idx & 31;
            int gr = row0 + rr;
            uint32_t dst = sbase + (uint32_t)(stage * BM * LDSX + rr * LDSX) * 4
                                 + (uint32_t)c4 * 16;
            const float* src = X + (size_t)gr * HID + c4 * 4;
            int sz = (gr < E) ? 16 : 0;          // zfill past E
            cp_async16(dst, src, sz);
        }
    };

    // prologue
    load_tile(0, t);
    asm volatile("cp.async.commit_group;\n");

    int s = 0;
    for (; t < ntiles; t += stride) {
        const int tn = t + stride;
        if (tn < ntiles) load_tile(s ^ 1, tn);
        asm volatile("cp.async.commit_group;\n");   // always commit (may be empty)
        asm volatile("cp.async.wait_group 1;\n");   // stage s ready, next in flight
        __syncthreads();

        const float* Xt = Xs + s * BM * LDSX;

        float acc[2][4][4];
        #pragma unroll
        for (int mt = 0; mt < 2; ++mt)
            #pragma unroll
            for (int nt = 0; nt < 4; ++nt)
                #pragma unroll
                for (int q = 0; q < 4; ++q) acc[mt][nt][q] = 0.f;

        #pragma unroll
        for (int ks = 0; ks < 16; ++ks) {
            uint32_t a[2][4];
            #pragma unroll
            for (int mt = 0; mt < 2; ++mt) {
                const float* base = Xt + (wm * 32 + mt * 16 + lq) * LDSX + ks * 8 + lr;
                // feed f32 bits directly; tensor core truncates to tf32
                a[mt][0] = __float_as_uint(base[0]);
                a[mt][1] = __float_as_uint(base[8 * LDSX]);
                a[mt][2] = __float_as_uint(base[4]);
                a[mt][3] = __float_as_uint(base[8 * LDSX + 4]);
            }
            #pragma unroll
            for (int nt = 0; nt < 4; ++nt) {
                const int gnt = wn * 4 + nt;
                float2 bb = bfr[(ks * 16 + gnt) * 32 + lane];
                uint32_t b0 = __float_as_uint(bb.x);
                uint32_t b1 = __float_as_uint(bb.y);
                #pragma unroll
                for (int mt = 0; mt < 2; ++mt) {
                    asm volatile(
                        "mma.sync.aligned.m16n8k8.row.col.f32.tf32.tf32.f32 "
                        "{%0,%1,%2,%3}, {%4,%5,%6,%7}, {%8,%9}, {%0,%1,%2,%3};\n"
                        : "+f"(acc[mt][nt][0]), "+f"(acc[mt][nt][1]),
                          "+f"(acc[mt][nt][2]), "+f"(acc[mt][nt][3])
                        : "r"(a[mt][0]), "r"(a[mt][1]), "r"(a[mt][2]), "r"(a[mt][3]),
                          "r"(b0), "r"(b1));
                }
            }
        }

        // epilogue: residual (fp32 from smem) + bias
        const int row0 = t * BM;
        #pragma unroll
        for (int mt = 0; mt < 2; ++mt) {
            const int r = wm * 32 + mt * 16 + lq;
            const int g0 = row0 + r, g1 = g0 + 8;
            const float* xr0 = Xt + r * LDSX;
            const float* xr1 = xr0 + 8 * LDSX;
            #pragma unroll
            for (int nt = 0; nt < 4; ++nt) {
                const int col = wn * 32 + nt * 8 + lr * 2;
                if (g0 < E) {
                    float2 o;
                    o.x = xr0[col]     + acc[mt][nt][0] + cv[nt][0];
                    o.y = xr0[col + 1] + acc[mt][nt][1] + cv[nt][1];
                    *reinterpret_cast<float2*>(Y + (size_t)g0 * HID + col) = o;
                }
                if (g1 < E) {
                    float2 o;
                    o.x = xr1[col]     + acc[mt][nt][2] + cv[nt][0];
                    o.y = xr1[col + 1] + acc[mt][nt][3] + cv[nt][1];
                    *reinterpret_cast<float2*>(Y + (size_t)g1 * HID + col) = o;
                }
            }
        }
        __syncthreads();   // stage s may be overwritten next iteration
        s ^= 1;
    }
}

// ---------------- launch ----------------
extern "C" void kernel_launch(void* const* d_in, const int* in_sizes, int n_in,
                              void* d_out, int out_size)
{
    const float* X    = (const float*)d_in[0];
    const float* Wv   = (const float*)d_in[7];
    const float* bv   = (const float*)d_in[8];
    const float* W_in = (const float*)d_in[9];
    const float* b_in = (const float*)d_in[10];
    const float* W_mo = (const float*)d_in[11];
    const float* b_mo = (const float*)d_in[12];
    const float* Wo   = (const float*)d_in[13];
    const float* bo   = (const float*)d_in[14];
    float* Y = (float*)d_out;

    const int E = in_sizes[0] / HID;
    const int ntiles = (E + BM - 1) / BM;

    prep1<<<HID, 256>>>(Wo, W_mo, W_in, Wv, bv, b_in, b_mo, bo);
    prep2<<<HID, 128>>>();

    const int smem = 2 * BM * LDSX * 4;  // 67,584 bytes
    cudaFuncSetAttribute(fused_main, cudaFuncAttributeMaxDynamicSharedMemorySize, smem);
    fused_main<<<PBLOCKS, NTHREADS, smem>>>(X, Y, E, ntiles);
}

// round 3
// speedup vs baseline: 1.1948x; 1.0140x over previous
#include <cuda_runtime.h>
#include <cstdint>
#include <cstddef>

#define HID 128
#define LDSX 132          // padded row stride (floats)
#define BM 64             // rows per tile
#define NTHREADS 256
#define PBLOCKS 444       // 3 per SM * 148 SMs, persistent

// ---------------- device scratch ----------------
__device__ float g_A[HID * HID];            // Wo @ W_mo
__device__ float g_B[HID * HID];            // Wiv @ Wv
__device__ float g_u[HID];                  // Wiv @ bv + biv
__device__ float g_w[HID];                  // Wo @ b_mo + bo
__device__ float g_Bfrag[16 * 16 * 32 * 2]; // 0.5*M^T, tf32, mma-fragment layout
__device__ float g_c[HID];                  // 0.5 * (A @ u + w)

__device__ __forceinline__ uint32_t f2tf32(float x) {
    uint32_t r;
    asm("cvt.rna.tf32.f32 %0, %1;" : "=r"(r) : "f"(x));
    return r;
}

// ---------------- prep1: A = Wo@W_mo, B = Wiv@Wv, u, w (128 blocks) -------
__global__ __launch_bounds__(256) void prep1(
    const float* __restrict__ Wo, const float* __restrict__ W_mo,
    const float* __restrict__ W_in, const float* __restrict__ Wv,
    const float* __restrict__ bv, const float* __restrict__ b_in,
    const float* __restrict__ b_mo, const float* __restrict__ bo)
{
    __shared__ float sWo[HID];
    __shared__ float sWiv[HID];
    const int r = blockIdx.x;
    const int t = threadIdx.x;

    if (t < HID) sWo[t] = Wo[r * HID + t];
    else         sWiv[t - HID] = W_in[(256 + r) * HID + (t - HID)];
    __syncthreads();

    if (t < HID) {
        float s0 = 0.f, s1 = 0.f, s2 = 0.f, s3 = 0.f;
        #pragma unroll
        for (int j = 0; j < HID; j += 4) {
            s0 += sWo[j]     * W_mo[j * HID + t];
            s1 += sWo[j + 1] * W_mo[(j + 1) * HID + t];
            s2 += sWo[j + 2] * W_mo[(j + 2) * HID + t];
            s3 += sWo[j + 3] * W_mo[(j + 3) * HID + t];
        }
        g_A[r * HID + t] = (s0 + s1) + (s2 + s3);
        if (t == 0) {
            float a0 = 0.f, a1 = 0.f, a2 = 0.f, a3 = 0.f;
            #pragma unroll
            for (int j = 0; j < HID; j += 4) {
                a0 += sWiv[j] * bv[j];     a1 += sWiv[j + 1] * bv[j + 1];
                a2 += sWiv[j + 2] * bv[j + 2]; a3 += sWiv[j + 3] * bv[j + 3];
            }
            g_u[r] = (a0 + a1) + (a2 + a3) + b_in[256 + r];
        }
    } else {
        const int c = t - HID;
        float s0 = 0.f, s1 = 0.f, s2 = 0.f, s3 = 0.f;
        #pragma unroll
        for (int j = 0; j < HID; j += 4) {
            s0 += sWiv[j]     * Wv[j * HID + c];
            s1 += sWiv[j + 1] * Wv[(j + 1) * HID + c];
            s2 += sWiv[j + 2] * Wv[(j + 2) * HID + c];
            s3 += sWiv[j + 3] * Wv[(j + 3) * HID + c];
        }
        g_B[r * HID + c] = (s0 + s1) + (s2 + s3);
        if (c == 0) {
            float a0 = 0.f, a1 = 0.f, a2 = 0.f, a3 = 0.f;
            #pragma unroll
            for (int j = 0; j < HID; j += 4) {
                a0 += sWo[j] * b_mo[j];     a1 += sWo[j + 1] * b_mo[j + 1];
                a2 += sWo[j + 2] * b_mo[j + 2]; a3 += sWo[j + 3] * b_mo[j + 3];
            }
            g_w[r] = (a0 + a1) + (a2 + a3) + bo[r];
        }
    }
}

// ---------------- prep2: M = 0.5*A@B -> fragment layout; c (128 blocks) ---
__global__ __launch_bounds__(128) void prep2()
{
    __shared__ float sA[HID];
    const int o = blockIdx.x;
    const int i = threadIdx.x;

    sA[i] = g_A[o * HID + i];
    __syncthreads();

    float s0 = 0.f, s1 = 0.f, s2 = 0.f, s3 = 0.f;
    #pragma unroll
    for (int j = 0; j < HID; j += 4) {
        s0 += sA[j]     * g_B[j * HID + i];
        s1 += sA[j + 1] * g_B[(j + 1) * HID + i];
        s2 += sA[j + 2] * g_B[(j + 2) * HID + i];
        s3 += sA[j + 3] * g_B[(j + 3) * HID + i];
    }
    float m = 0.5f * ((s0 + s1) + (s2 + s3));

    // scatter M'[o][i] into the mma B-fragment layout:
    //   ks = i>>3, lr = i&3, half = (i>>2)&1, nt = o>>3, lq = o&7
    const int nt = o >> 3, lq = o & 7;
    const int ks = i >> 3, lr = i & 3, half = (i >> 2) & 1;
    g_Bfrag[(((ks * 16 + nt) * 32) + lq * 4 + lr) * 2 + half] =
        __uint_as_float(f2tf32(m));

    if (i == 0) {
        float a0 = 0.f, a1 = 0.f, a2 = 0.f, a3 = 0.f;
        #pragma unroll
        for (int j = 0; j < HID; j += 4) {
            a0 += sA[j] * g_u[j];     a1 += sA[j + 1] * g_u[j + 1];
            a2 += sA[j + 2] * g_u[j + 2]; a3 += sA[j + 3] * g_u[j + 3];
        }
        g_c[o] = 0.5f * (((a0 + a1) + (a2 + a3)) + g_w[o]);
    }
}

// ---------------- main: Y = X + X@M'^T + c, persistent + double-buffered --
__device__ __forceinline__ void cp_async16(uint32_t dst, const void* src, int sz) {
    asm volatile("cp.async.cg.shared.global [%0], [%1], 16, %2;\n"
                 :: "r"(dst), "l"(src), "r"(sz));
}

__global__ __launch_bounds__(NTHREADS, 3) void fused_main(
    const float* __restrict__ X, float* __restrict__ Y, int E, int ntiles)
{
    extern __shared__ float Xs[];  // 2 stages x [BM][LDSX]
    const int tid  = threadIdx.x;
    const int lane = tid & 31, wid = tid >> 5;
    const int wm = wid & 1, wn = wid >> 1;          // 2(m) x 4(n) warp grid
    const int lq = lane >> 2, lr = lane & 3;

    uint32_t sbase;
    asm("{ .reg .u64 t; cvta.to.shared.u64 t, %1; cvt.u32.u64 %0, t; }"
        : "=r"(sbase) : "l"(Xs));

    const float2* bfr = reinterpret_cast<const float2*>(g_Bfrag);

    // per-thread output bias (constant across tiles)
    float cv[4][2];
    #pragma unroll
    for (int nt = 0; nt < 4; ++nt) {
        int col = wn * 32 + nt * 8 + lr * 2;
        cv[nt][0] = g_c[col];
        cv[nt][1] = g_c[col + 1];
    }

    int t = blockIdx.x;
    const int stride = gridDim.x;
    if (t >= ntiles) return;

    // --- async tile loader: 8 x 16B per thread = 32KB tile ---
    auto load_tile = [&](int stage, int tt) {
        const int row0 = tt * BM;
        #pragma unroll
        for (int it = 0; it < 8; ++it) {
            int idx = it * NTHREADS + tid;       // 0..2047
            int rr = idx >> 5, c4 = idx & 31;
            int gr = row0 + rr;
            uint32_t dst = sbase + (uint32_t)(stage * BM * LDSX + rr * LDSX) * 4
                                 + (uint32_t)c4 * 16;
            const float* src = X + (size_t)gr * HID + c4 * 4;
            int sz = (gr < E) ? 16 : 0;          // zfill past E
            cp_async16(dst, src, sz);
        }
    };

    // prologue
    load_tile(0, t);
    asm volatile("cp.async.commit_group;\n");

    int s = 0;
    for (; t < ntiles; t += stride) {
        const int tn = t + stride;
        if (tn < ntiles) load_tile(s ^ 1, tn);
        asm volatile("cp.async.commit_group;\n");   // always commit (may be empty)
        asm volatile("cp.async.wait_group 1;\n");   // stage s ready, next in flight
        __syncthreads();

        const float* Xt = Xs + s * BM * LDSX;

        float acc[2][4][4];
        #pragma unroll
        for (int mt = 0; mt < 2; ++mt)
            #pragma unroll
            for (int nt = 0; nt < 4; ++nt)
                #pragma unroll
                for (int q = 0; q < 4; ++q) acc[mt][nt][q] = 0.f;

        #pragma unroll
        for (int ks = 0; ks < 16; ++ks) {
            uint32_t a[2][4];
            #pragma unroll
            for (int mt = 0; mt < 2; ++mt) {
                const float* base = Xt + (wm * 32 + mt * 16 + lq) * LDSX + ks * 8 + lr;
                // feed f32 bits directly; tensor core truncates to tf32
                a[mt][0] = __float_as_uint(base[0]);
                a[mt][1] = __float_as_uint(base[8 * LDSX]);
                a[mt][2] = __float_as_uint(base[4]);
                a[mt][3] = __float_as_uint(base[8 * LDSX + 4]);
            }
            #pragma unroll
            for (int nt = 0; nt < 4; ++nt) {
                const int gnt = wn * 4 + nt;
                float2 bb = bfr[(ks * 16 + gnt) * 32 + lane];
                uint32_t b0 = __float_as_uint(bb.x);
                uint32_t b1 = __float_as_uint(bb.y);
                #pragma unroll
                for (int mt = 0; mt < 2; ++mt) {
                    asm volatile(
                        "mma.sync.aligned.m16n8k8.row.col.f32.tf32.tf32.f32 "
                        "{%0,%1,%2,%3}, {%4,%5,%6,%7}, {%8,%9}, {%0,%1,%2,%3};\n"
                        : "+f"(acc[mt][nt][0]), "+f"(acc[mt][nt][1]),
                          "+f"(acc[mt][nt][2]), "+f"(acc[mt][nt][3])
                        : "r"(a[mt][0]), "r"(a[mt][1]), "r"(a[mt][2]), "r"(a[mt][3]),
                          "r"(b0), "r"(b1));
                }
            }
        }

        // epilogue: residual (fp32 from smem) + bias
        const int row0 = t * BM;
        #pragma unroll
        for (int mt = 0; mt < 2; ++mt) {
            const int r = wm * 32 + mt * 16 + lq;
            const int g0 = row0 + r, g1 = g0 + 8;
            const float* xr0 = Xt + r * LDSX;
            const float* xr1 = xr0 + 8 * LDSX;
            #pragma unroll
            for (int nt = 0; nt < 4; ++nt) {
                const int col = wn * 32 + nt * 8 + lr * 2;
                if (g0 < E) {
                    float2 o;
                    o.x = xr0[col]     + acc[mt][nt][0] + cv[nt][0];
                    o.y = xr0[col + 1] + acc[mt][nt][1] + cv[nt][1];
                    *reinterpret_cast<float2*>(Y + (size_t)g0 * HID + col) = o;
                }
                if (g1 < E) {
                    float2 o;
                    o.x = xr1[col]     + acc[mt][nt][2] + cv[nt][0];
                    o.y = xr1[col + 1] + acc[mt][nt][3] + cv[nt][1];
                    *reinterpret_cast<float2*>(Y + (size_t)g1 * HID + col) = o;
                }
            }
        }
        __syncthreads();   // stage s may be overwritten next iteration
        s ^= 1;
    }
}

// ---------------- launch ----------------
extern "C" void kernel_launch(void* const* d_in, const int* in_sizes, int n_in,
                              void* d_out, int out_size)
{
    const float* X    = (const float*)d_in[0];
    const float* Wv   = (const float*)d_in[7];
    const float* bv   = (const float*)d_in[8];
    const float* W_in = (const float*)d_in[9];
    const float* b_in = (const float*)d_in[10];
    const float* W_mo = (const float*)d_in[11];
    const float* b_mo = (const float*)d_in[12];
    const float* Wo   = (const float*)d_in[13];
    const float* bo   = (const float*)d_in[14];
    float* Y = (float*)d_out;

    const int E = in_sizes[0] / HID;
    const int ntiles = (E + BM - 1) / BM;

    prep1<<<HID, 256>>>(Wo, W_mo, W_in, Wv, bv, b_in, b_mo, bo);
    prep2<<<HID, 128>>>();

    const int smem = 2 * BM * LDSX * 4;  // 67,584 bytes
    cudaFuncSetAttribute(fused_main, cudaFuncAttributeMaxDynamicSharedMemorySize, smem);
    fused_main<<<PBLOCKS, NTHREADS, smem>>>(X, Y, E, ntiles);
}

// round 5
// speedup vs baseline: 1.8650x; 1.5610x over previous
#include <cuda_runtime.h>
#include <cuda.h>
#include <cuda_bf16.h>
#include <cstdint>
#include <cstddef>

#define HID 128
#define BM 128
#define TILE_BYTES 65536
#define GRID 148
#define NTHREADS 256

// ---------------- device scratch ----------------
__device__ float g_A[HID * HID];                 // Wo @ W_mo
__device__ float g_B[HID * HID];                 // Wiv @ Wv
__device__ float g_u[HID];
__device__ float g_w[HID];
__device__ __nv_bfloat16 g_Bf[16 * 8 * 2 * 32 * 2]; // 0.5*M^T bf16, mma-B-fragment layout
__device__ float g_c[HID];                       // 0.5*(A@u + w)

__device__ __forceinline__ uint32_t smem_u32(const void* p) {
    uint32_t a;
    asm("{ .reg .u64 t; cvta.to.shared.u64 t, %1; cvt.u32.u64 %0, t; }" : "=r"(a) : "l"(p));
    return a;
}
__device__ __forceinline__ float warp_red(float p) {
    p += __shfl_xor_sync(0xffffffffu, p, 16);
    p += __shfl_xor_sync(0xffffffffu, p, 8);
    p += __shfl_xor_sync(0xffffffffu, p, 4);
    p += __shfl_xor_sync(0xffffffffu, p, 2);
    p += __shfl_xor_sync(0xffffffffu, p, 1);
    return p;
}

// ================= prep1: A = Wo@W_mo, B = Wiv@Wv, u, w ===================
__global__ __launch_bounds__(256) void prep1(
    const float* __restrict__ Wo, const float* __restrict__ W_mo,
    const float* __restrict__ W_in, const float* __restrict__ Wv,
    const float* __restrict__ bv, const float* __restrict__ b_in,
    const float* __restrict__ b_mo, const float* __restrict__ bo)
{
    __shared__ float sWo[HID], sWiv[HID];
    __shared__ float sM[32 * HID], sV[32 * HID];
    const int r = blockIdx.x, t = threadIdx.x;

    if (t < HID) sWo[t] = Wo[r * HID + t];
    else         sWiv[t - HID] = W_in[(256 + r) * HID + (t - HID)];

    const float4* Wm4 = reinterpret_cast<const float4*>(W_mo);
    const float4* Wv4 = reinterpret_cast<const float4*>(Wv);
    float4* sM4 = reinterpret_cast<float4*>(sM);
    float4* sV4 = reinterpret_cast<float4*>(sV);

    float acc = 0.f;
    for (int ch = 0; ch < 4; ++ch) {
        __syncthreads();
        const int b4 = ch * 1024;
        #pragma unroll
        for (int q = 0; q < 4; ++q) {
            int idx = q * 256 + t;
            sM4[idx] = Wm4[b4 + idx];
            sV4[idx] = Wv4[b4 + idx];
        }
        __syncthreads();
        if (t < HID) {
            #pragma unroll
            for (int j = 0; j < 32; ++j) acc += sWo[ch * 32 + j] * sM[j * HID + t];
        } else {
            const int c = t - HID;
            #pragma unroll
            for (int j = 0; j < 32; ++j) acc += sWiv[ch * 32 + j] * sV[j * HID + c];
        }
    }
    if (t < HID) g_A[r * HID + t] = acc;
    else         g_B[r * HID + (t - HID)] = acc;

    if (t < 32) {
        float p = 0.f;
        #pragma unroll
        for (int j = t; j < HID; j += 32) p += sWiv[j] * bv[j];
        p = warp_red(p);
        if (t == 0) g_u[r] = p + b_in[256 + r];
    } else if (t < 64) {
        const int l = t - 32;
        float p = 0.f;
        #pragma unroll
        for (int j = l; j < HID; j += 32) p += sWo[j] * b_mo[j];
        p = warp_red(p);
        if (l == 0) g_w[r] = p + bo[r];
    }
}

// ================= prep2: Bf = bf16(0.5*A@B) in B-fragment layout; c ======
// mma.m16n8k16.row.col B fragment (per 16k x 8n tile): lane L holds
//   reg0 = { B[k0][n], B[k0+1][n] },  reg1 = { B[k0+8][n], B[k0+9][n] }
//   with k0 = 2*(L&3), n = L>>2 ;  B[k][n] := M'[n][k]
__global__ __launch_bounds__(256) void prep2()
{
    __shared__ float sA[HID];
    __shared__ float sB[32 * HID];
    const int o = blockIdx.x, t = threadIdx.x;

    if (t < HID) sA[t] = g_A[o * HID + t];
    const float4* gB4 = reinterpret_cast<const float4*>(g_B);
    float4* sB4 = reinterpret_cast<float4*>(sB);

    float acc = 0.f;
    for (int ch = 0; ch < 4; ++ch) {
        __syncthreads();
        #pragma unroll
        for (int q = 0; q < 4; ++q) {
            int idx = q * 256 + t;
            sB4[idx] = gB4[ch * 1024 + idx];
        }
        __syncthreads();
        if (t < HID) {
            #pragma unroll
            for (int j = 0; j < 32; ++j) acc += sA[ch * 32 + j] * sB[j * HID + t];
        }
    }
    if (t < HID) {
        const float m = 0.5f * acc;
        const int i = t;                 // k index
        const int nt = o >> 3;           // n-tile (8 wide)
        const int ks = i >> 4;           // k-chunk (16 deep)
        const int r  = i & 15;
        const int regi = (r >> 3) & 1;
        const int half = r & 1;
        const int lane = ((o & 7) << 2) | ((r & 7) >> 1);
        const int idx = ((((nt * 8 + ks) * 2 + regi) * 32) + lane) * 2 + half;
        g_Bf[idx] = __float2bfloat16(m);
    }

    if (t < 32) {
        float p = 0.f;
        #pragma unroll
        for (int j = t; j < HID; j += 32) p += sA[j] * g_u[j];
        p = warp_red(p);
        if (t == 0) g_c[o] = 0.5f * (p + g_w[o]);
    }
}

// ================= main =====================================================
// smem: XS0 @0 (64KB fp32 SW128), XS1 @65536, XB @131072 (32KB bf16 swizzled),
//       mbar full0/full1 @163840/163848
#define OFF_XS0  0u
#define OFF_XS1  65536u
#define OFF_XB   131072u
#define OFF_MBAR 163840u
#define SMEM_TOTAL 163968

#define MBAR_INIT(a, c) \
    asm volatile("mbarrier.init.shared.b64 [%0], %1;" :: "r"(a), "r"(c) : "memory")
#define MBAR_EXPECT(a, b) \
    asm volatile("mbarrier.arrive.expect_tx.shared.b64 _, [%0], %1;" :: "r"(a), "r"(b) : "memory")
#define MBAR_WAIT(mbar, par) do {                                             \
    uint32_t _m = (mbar); uint32_t _p = (par); uint32_t _d;                   \
    asm volatile("{\n\t.reg .pred p;\n\t"                                     \
        "mbarrier.try_wait.parity.acquire.cta.shared::cta.b64 p, [%1], %2;\n\t" \
        "selp.b32 %0, 1, 0, p;\n\t}"                                          \
        : "=r"(_d) : "r"(_m), "r"(_p) : "memory");                            \
    if (!_d) {                                                                \
        asm volatile("{\n\t.reg .pred P1;\n\t"                                \
            "W_%=:\n\t"                                                       \
            "mbarrier.try_wait.parity.acquire.cta.shared::cta.b64 P1, [%0], %1, 0x989680;\n\t" \
            "@P1 bra.uni D_%=;\n\t"                                           \
            "bra.uni W_%=;\n\t"                                               \
            "D_%=:\n\t}" :: "r"(_m), "r"(_p) : "memory");                     \
    }                                                                         \
} while (0)

#define TMA_LOAD2D(dst, map, x, y, mb) \
    asm volatile("cp.async.bulk.tensor.2d.shared::cta.global.tile.mbarrier::complete_tx::bytes " \
                 "[%0], [%1, {%2, %3}], [%4];" \
                 :: "r"(dst), "l"(map), "r"(x), "r"(y), "r"(mb) : "memory")
#define TMA_STORE2D(map, x, y, src) \
    asm volatile("cp.async.bulk.tensor.2d.global.shared::cta.tile.bulk_group " \
                 "[%0, {%1, %2}], [%3];" \
                 :: "l"(map), "r"(x), "r"(y), "r"(src) : "memory")
#define FENCE_ASYNC() asm volatile("fence.proxy.async.shared::cta;" ::: "memory")

__device__ __forceinline__ uint32_t packbf(float lo, float hi) {
    uint32_t d;
    asm("cvt.rn.bf16x2.f32 %0, %1, %2;" : "=r"(d) : "f"(hi), "f"(lo));
    return d;
}

__global__ __launch_bounds__(NTHREADS, 1) void fused_main(
    const __grid_constant__ CUtensorMap tmX,
    const __grid_constant__ CUtensorMap tmY,
    int ntiles)
{
    extern __shared__ __align__(1024) unsigned char smem_raw[];
    const uint32_t sb = smem_u32(smem_raw);
    const int tid  = threadIdx.x;
    const int lane = tid & 31, wid = tid >> 5;
    const int wm = wid & 1, wn = wid >> 1;      // 2(m) x 4(n) warp grid
    const uint32_t mb_full[2] = { sb + OFF_MBAR, sb + OFF_MBAR + 8 };
    const uint32_t xb = sb + OFF_XB;

    // ---- B fragments into registers (constant across tiles) ----
    uint32_t breg[4][8][2];
    {
        const uint32_t* bp = reinterpret_cast<const uint32_t*>(g_Bf);
        #pragma unroll
        for (int nt = 0; nt < 4; ++nt)
            #pragma unroll
            for (int ks = 0; ks < 8; ++ks)
                #pragma unroll
                for (int ri = 0; ri < 2; ++ri)
                    breg[nt][ks][ri] =
                        bp[(((wn * 4 + nt) * 8 + ks) * 2 + ri) * 32 + lane];
    }
    // ---- c bias (per-thread cols) ----
    float cv[4][2];
    #pragma unroll
    for (int nt = 0; nt < 4; ++nt) {
        const int col = wn * 32 + nt * 8 + 2 * (lane & 3);
        cv[nt][0] = g_c[col];
        cv[nt][1] = g_c[col + 1];
    }

    if (tid == 0) { MBAR_INIT(mb_full[0], 1); MBAR_INIT(mb_full[1], 1); }
    __syncthreads();

    const int bid = blockIdx.x;
    if (tid == 0 && bid < ntiles) {
        MBAR_EXPECT(mb_full[0], TILE_BYTES);
        #pragma unroll
        for (int ac = 0; ac < 4; ++ac)
            TMA_LOAD2D(sb + OFF_XS0 + ac * 16384, &tmX, ac * 32, bid * BM, mb_full[0]);
    }

    // per-thread constants for the convert pass
    const int crow = tid >> 1, ch = tid & 1;
    const uint32_t cr7 = (uint32_t)(crow & 7);
    // ldmatrix constants
    const int rsub = lane & 15;
    const uint32_t lr7 = (uint32_t)(rsub & 7);
    const int khalf = lane >> 4;
    // epilogue constants
    const uint32_t er7a = (uint32_t)(lane >> 2);        // rowA & 7
    const uint32_t einner = (uint32_t)(lane & 1) * 8;
    const uint32_t eq16b = (uint32_t)((lane & 3) >> 1); // sub-chunk from col

    unsigned ph = 0;
    int t = bid;
    for (int i = 0; t < ntiles; ++i, t += GRID) {
        const int s = i & 1;
        const uint32_t xs = sb + (s ? OFF_XS1 : OFF_XS0);

        // wait X tile
        MBAR_WAIT(mb_full[s], (ph >> s) & 1);
        ph ^= (1u << s);

        // ---- convert fp32 XS[s] -> bf16 XB (swizzled 256B rows) ----
        {
            const uint32_t rxs = xs + (uint32_t)crow * 128;
            const uint32_t rxb = xb + (uint32_t)crow * 256;
            #pragma unroll
            for (int j = 0; j < 8; ++j) {
                const int cj = ch * 8 + j;
                const uint32_t c32 = (uint32_t)(cj >> 2) * 16384;
                const uint32_t q0 = (uint32_t)((cj & 3) * 2);
                const uint32_t a0 = rxs + c32 + ((q0 ^ cr7) << 4);
                const uint32_t a1 = rxs + c32 + (((q0 + 1) ^ cr7) << 4);
                float x0, x1, x2, x3, y0, y1, y2, y3;
                asm volatile("ld.shared.v4.f32 {%0,%1,%2,%3}, [%4];"
                             : "=f"(x0), "=f"(x1), "=f"(x2), "=f"(x3) : "r"(a0));
                asm volatile("ld.shared.v4.f32 {%0,%1,%2,%3}, [%4];"
                             : "=f"(y0), "=f"(y1), "=f"(y2), "=f"(y3) : "r"(a1));
                const uint32_t p0 = packbf(x0, x1), p1 = packbf(x2, x3);
                const uint32_t p2 = packbf(y0, y1), p3 = packbf(y2, y3);
                const uint32_t ab = rxb + (((uint32_t)cj ^ cr7) << 4);
                asm volatile("st.shared.v4.b32 [%0], {%1,%2,%3,%4};"
                             :: "r"(ab), "r"(p0), "r"(p1), "r"(p2), "r"(p3) : "memory");
            }
        }
        __syncthreads();

        // ---- prefetch next tile into the other stage ----
        if (tid == 0) {
            const int tn = t + GRID;
            if (tn < ntiles) {
                // make sure the TMA store that read XS[s^1] (tile t-1) drained
                asm volatile("cp.async.bulk.wait_group.read 0;" ::: "memory");
                MBAR_EXPECT(mb_full[s ^ 1], TILE_BYTES);
                const uint32_t xo = sb + (s ? OFF_XS0 : OFF_XS1);
                #pragma unroll
                for (int ac = 0; ac < 4; ++ac)
                    TMA_LOAD2D(xo + ac * 16384, &tmX, ac * 32, tn * BM, mb_full[s ^ 1]);
            }
        }

        // ---- mma mainloop: acc = bf16(X) @ B ----
        float acc[4][4][4];
        #pragma unroll
        for (int mt = 0; mt < 4; ++mt)
            #pragma unroll
            for (int nt = 0; nt < 4; ++nt)
                #pragma unroll
                for (int q = 0; q < 4; ++q) acc[mt][nt][q] = 0.f;

        #pragma unroll
        for (int ks = 0; ks < 8; ++ks) {
            uint32_t a[4][4];
            const uint32_t chunk = (uint32_t)(2 * ks + khalf);
            const uint32_t csw = (chunk ^ lr7) << 4;
            #pragma unroll
            for (int mt = 0; mt < 4; ++mt) {
                const uint32_t addr =
                    xb + (uint32_t)(wm * 64 + mt * 16 + rsub) * 256 + csw;
                asm volatile("ldmatrix.sync.aligned.m8n8.x4.shared.b16 {%0,%1,%2,%3}, [%4];"
                             : "=r"(a[mt][0]), "=r"(a[mt][1]), "=r"(a[mt][2]), "=r"(a[mt][3])
                             : "r"(addr));
            }
            #pragma unroll
            for (int mt = 0; mt < 4; ++mt)
                #pragma unroll
                for (int nt = 0; nt < 4; ++nt) {
                    asm volatile(
                        "mma.sync.aligned.m16n8k16.row.col.f32.bf16.bf16.f32 "
                        "{%0,%1,%2,%3}, {%4,%5,%6,%7}, {%8,%9}, {%0,%1,%2,%3};"
                        : "+f"(acc[mt][nt][0]), "+f"(acc[mt][nt][1]),
                          "+f"(acc[mt][nt][2]), "+f"(acc[mt][nt][3])
                        : "r"(a[mt][0]), "r"(a[mt][1]), "r"(a[mt][2]), "r"(a[mt][3]),
                          "r"(breg[nt][ks][0]), "r"(breg[nt][ks][1]));
                }
        }

        // ---- epilogue: Y = X + acc + c, in place in XS[s] ----
        {
            const uint32_t xsn = xs + (uint32_t)wn * 16384;
            #pragma unroll
            for (int mt = 0; mt < 4; ++mt) {
                const uint32_t rA = (uint32_t)(wm * 64 + mt * 16) + (uint32_t)(lane >> 2);
                const uint32_t rB = rA + 8;
                const uint32_t baseA = xsn + rA * 128;
                const uint32_t baseB = xsn + rB * 128;
                #pragma unroll
                for (int nt = 0; nt < 4; ++nt) {
                    const uint32_t q16 = (uint32_t)(nt * 2) + eq16b;
                    const uint32_t aA = baseA + ((q16 ^ er7a) << 4) + einner;
                    const uint32_t aB = baseB + ((q16 ^ er7a) << 4) + einner;
                    float f0, f1;
                    asm volatile("ld.shared.v2.f32 {%0,%1}, [%2];"
                                 : "=f"(f0), "=f"(f1) : "r"(aA));
                    f0 += acc[mt][nt][0] + cv[nt][0];
                    f1 += acc[mt][nt][1] + cv[nt][1];
                    asm volatile("st.shared.v2.f32 [%0], {%1,%2};"
                                 :: "r"(aA), "f"(f0), "f"(f1) : "memory");
                    asm volatile("ld.shared.v2.f32 {%0,%1}, [%2];"
                                 : "=f"(f0), "=f"(f1) : "r"(aB));
                    f0 += acc[mt][nt][2] + cv[nt][0];
                    f1 += acc[mt][nt][3] + cv[nt][1];
                    asm volatile("st.shared.v2.f32 [%0], {%1,%2};"
                                 :: "r"(aB), "f"(f0), "f"(f1) : "memory");
                }
            }
        }
        FENCE_ASYNC();
        __syncthreads();

        if (tid == 0) {
            #pragma unroll
            for (int ac = 0; ac < 4; ++ac)
                TMA_STORE2D(&tmY, ac * 32, t * BM, xs + ac * 16384);
            asm volatile("cp.async.bulk.commit_group;" ::: "memory");
        }
        __syncthreads();   // XB reuse next iteration only after all read it
    }

    if (tid == 0)
        asm volatile("cp.async.bulk.wait_group 0;" ::: "memory");
}

// ================= host ====================================================
typedef CUresult (*PFN_encodeTiled)(
    CUtensorMap*, CUtensorMapDataType, cuuint32_t, void*,
    const cuuint64_t*, const cuuint64_t*, const cuuint32_t*, const cuuint32_t*,
    CUtensorMapInterleave, CUtensorMapSwizzle, CUtensorMapL2promotion,
    CUtensorMapFloatOOBfill);

extern "C" void kernel_launch(void* const* d_in, const int* in_sizes, int n_in,
                              void* d_out, int out_size)
{
    const float* X    = (const float*)d_in[0];
    const float* Wv   = (const float*)d_in[7];
    const float* bv   = (const float*)d_in[8];
    const float* W_in = (const float*)d_in[9];
    const float* b_in = (const float*)d_in[10];
    const float* W_mo = (const float*)d_in[11];
    const float* b_mo = (const float*)d_in[12];
    const float* Wo   = (const float*)d_in[13];
    const float* bo   = (const float*)d_in[14];
    float* Y = (float*)d_out;

    const int E = in_sizes[0] / HID;
    const int ntiles = (E + BM - 1) / BM;

    prep1<<<HID, 256>>>(Wo, W_mo, W_in, Wv, bv, b_in, b_mo, bo);
    prep2<<<HID, 256>>>();

    void* pfn = nullptr;
    cudaDriverEntryPointQueryResult qr;
    cudaGetDriverEntryPoint("cuTensorMapEncodeTiled", &pfn, cudaEnableDefault, &qr);
    PFN_encodeTiled encode = (PFN_encodeTiled)pfn;

    CUtensorMap tmX, tmY;
    cuuint64_t dims[2] = { (cuuint64_t)HID, (cuuint64_t)E };
    cuuint64_t str[1]  = { (cuuint64_t)HID * 4 };
    cuuint32_t box[2]  = { 32, 128 };
    cuuint32_t es[2]   = { 1, 1 };
    encode(&tmX, CU_TENSOR_MAP_DATA_TYPE_FLOAT32, 2, (void*)X,
           dims, str, box, es, CU_TENSOR_MAP_INTERLEAVE_NONE,
           CU_TENSOR_MAP_SWIZZLE_128B, CU_TENSOR_MAP_L2_PROMOTION_L2_128B,
           CU_TENSOR_MAP_FLOAT_OOB_FILL_NONE);
    encode(&tmY, CU_TENSOR_MAP_DATA_TYPE_FLOAT32, 2, (void*)Y,
           dims, str, box, es, CU_TENSOR_MAP_INTERLEAVE_NONE,
           CU_TENSOR_MAP_SWIZZLE_128B, CU_TENSOR_MAP_L2_PROMOTION_L2_128B,
           CU_TENSOR_MAP_FLOAT_OOB_FILL_NONE);

    cudaFuncSetAttribute(fused_main, cudaFuncAttributeMaxDynamicSharedMemorySize, SMEM_TOTAL);
    fused_main<<<GRID, NTHREADS, SMEM_TOTAL>>>(tmX, tmY, ntiles);
}